// round 1
// baseline (speedup 1.0000x reference)
#include <cuda_runtime.h>
#include <math_constants.h>

// ---------------------------------------------------------------------------
// EstimatorQNN, 2 qubits, 2 layers.
// Algebraic collapse:
//   encoded state psi = (c0,s0) (x) (c1,s1), real, c=cos(x*pi/2), s=sin(x*pi/2)
//   variational part = fixed 4x4 complex unitary U built from the 12 weights
//   <Z0> = psi^T * Re(U^H (Z (x) I) U) * psi   (symmetric real 4x4 form S)
// Setup kernel (1 thread) simulates the circuit on 4 basis columns to get U,
// builds the 10 packed coefficients of S (off-diagonals pre-doubled).
// Main kernel: grid-stride-free flat launch, float4 in (2 samples), float2 out.
// ---------------------------------------------------------------------------

__device__ float d_C[10];   // {S00,S11,S22,S33, 2*S01,2*S02,2*S03,2*S12,2*S13,2*S23}

struct Cx { float re, im; };

__device__ __forceinline__ Cx cmul(Cx a, Cx b) {
    Cx r; r.re = a.re * b.re - a.im * b.im; r.im = a.re * b.im + a.im * b.re; return r;
}
__device__ __forceinline__ Cx cadd(Cx a, Cx b) { Cx r; r.re = a.re + b.re; r.im = a.im + b.im; return r; }

// Apply 2x2 complex gate M to 4-amplitude state on qubit q.
// index k = 2*q0 + q1.
__device__ void apply_gate(Cx s[4], Cx m00, Cx m01, Cx m10, Cx m11, int q) {
    if (q == 0) {
        // pairs (0,2) and (1,3)
        for (int j = 0; j < 2; j++) {
            Cx a = s[j], b = s[j + 2];
            s[j]     = cadd(cmul(m00, a), cmul(m01, b));
            s[j + 2] = cadd(cmul(m10, a), cmul(m11, b));
        }
    } else {
        // pairs (0,1) and (2,3)
        for (int j = 0; j < 4; j += 2) {
            Cx a = s[j], b = s[j + 1];
            s[j]     = cadd(cmul(m00, a), cmul(m01, b));
            s[j + 1] = cadd(cmul(m10, a), cmul(m11, b));
        }
    }
}

__global__ void build_S_kernel(const float* __restrict__ w) {
    // Simulate variational circuit on the 4 computational basis columns.
    // U[k][b]: column b of the variational unitary.
    Cx U[4][4];
    for (int b = 0; b < 4; b++) {
        Cx s[4];
        for (int k = 0; k < 4; k++) { s[k].re = (k == b) ? 1.0f : 0.0f; s[k].im = 0.0f; }
        int off = 0;
        for (int layer = 0; layer < 2; layer++) {
            for (int q = 0; q < 2; q++) {
                float tx = w[off + q * 3 + 0];
                float tz = w[off + q * 3 + 1];
                float ty = w[off + q * 3 + 2];
                float c, sn;
                // RX(tx)
                c = cosf(0.5f * tx); sn = sinf(0.5f * tx);
                { Cx m00{c,0}, m01{0,-sn}, m10{0,-sn}, m11{c,0};
                  apply_gate(s, m00, m01, m10, m11, q); }
                // RZ(tz)
                c = cosf(0.5f * tz); sn = sinf(0.5f * tz);
                { Cx m00{c,-sn}, m01{0,0}, m10{0,0}, m11{c,sn};
                  apply_gate(s, m00, m01, m10, m11, q); }
                // RY(ty)
                c = cosf(0.5f * ty); sn = sinf(0.5f * ty);
                { Cx m00{c,0}, m01{-sn,0}, m10{sn,0}, m11{c,0};
                  apply_gate(s, m00, m01, m10, m11, q); }
            }
            // CNOT(control q0, target q1): swap k=2 and k=3
            Cx t = s[2]; s[2] = s[3]; s[3] = t;
            off += 6;
        }
        for (int k = 0; k < 4; k++) U[k][b] = s[k];
    }

    // S[i][j] = sum_k z_k * Re( conj(U[k][i]) * U[k][j] ),  z = {+1,+1,-1,-1}
    float S[4][4];
    for (int i = 0; i < 4; i++)
        for (int j = 0; j < 4; j++) {
            float acc = 0.0f;
            for (int k = 0; k < 4; k++) {
                float zk = (k < 2) ? 1.0f : -1.0f;
                acc += zk * (U[k][i].re * U[k][j].re + U[k][i].im * U[k][j].im);
            }
            S[i][j] = acc;
        }

    d_C[0] = S[0][0];
    d_C[1] = S[1][1];
    d_C[2] = S[2][2];
    d_C[3] = S[3][3];
    d_C[4] = 2.0f * S[0][1];
    d_C[5] = 2.0f * S[0][2];
    d_C[6] = 2.0f * S[0][3];
    d_C[7] = 2.0f * S[1][2];
    d_C[8] = 2.0f * S[1][3];
    d_C[9] = 2.0f * S[2][3];
}

__device__ __forceinline__ float eval_one(float x0, float x1, const float c[10]) {
    float s0, c0, s1, c1;
    sincospif(0.5f * x0, &s0, &c0);   // sin/cos of x0*pi/2
    sincospif(0.5f * x1, &s1, &c1);
    float p0 = c0 * c1;
    float p1 = c0 * s1;
    float p2 = s0 * c1;
    float p3 = s0 * s1;
    float r;
    r  = c[0] * p0 * p0;
    r += c[1] * p1 * p1;
    r += c[2] * p2 * p2;
    r += c[3] * p3 * p3;
    r += c[4] * p0 * p1;
    r += c[5] * p0 * p2;
    r += c[6] * p0 * p3;
    r += c[7] * p1 * p2;
    r += c[8] * p1 * p3;
    r += c[9] * p2 * p3;
    return r;
}

__global__ void __launch_bounds__(256) qnn_main_kernel(
    const float4* __restrict__ in, float2* __restrict__ out, int n_pairs) {
    int i = blockIdx.x * blockDim.x + threadIdx.x;
    float c[10];
#pragma unroll
    for (int j = 0; j < 10; j++) c[j] = d_C[j];
    if (i >= n_pairs) return;
    float4 x = in[i];             // two samples: (x0,x1) and (x0',x1')
    float2 r;
    r.x = eval_one(x.x, x.y, c);
    r.y = eval_one(x.z, x.w, c);
    out[i] = r;
}

extern "C" void kernel_launch(void* const* d_in, const int* in_sizes, int n_in,
                              void* d_out, int out_size) {
    const float* inputs  = (const float*)d_in[0];   // [B,2]
    const float* weights = (const float*)d_in[1];   // [12]
    float* out = (float*)d_out;                     // [B]

    build_S_kernel<<<1, 1>>>(weights);

    int B = in_sizes[0] / 2;
    int n_pairs = B / 2;                            // B = 4194304, even
    int threads = 256;
    int blocks = (n_pairs + threads - 1) / threads;
    qnn_main_kernel<<<blocks, threads>>>((const float4*)inputs, (float2*)out, n_pairs);
}

// round 3
// speedup vs baseline: 2.0077x; 2.0077x over previous
#include <cuda_runtime.h>
#include <math_constants.h>

// ---------------------------------------------------------------------------
// EstimatorQNN, 2 qubits, 2 layers — algebraic collapse + double-angle basis.
//
//   encoded state psi = (c0,s0) (x) (c1,s1),  c=cos(x*pi/2), s=sin(x*pi/2)
//   variational part = fixed 4x4 complex unitary U from the 12 weights
//   <Z0> = psi^T S psi,  S symmetric real 4x4.
// All monomials p_a p_b reduce via double angles to the 3x3 basis
//   {1, C0, S0} x {1, C1, S1},  C=cos(pi*x), S=sin(pi*x)
// giving r = sum of 9 fixed coefficients K — 2 fast sincos + 8 FMA / sample.
// ---------------------------------------------------------------------------

__device__ float d_K[9];  // {K1, KC1, KS1, KC0, KC0C1, KC0S1, KS0, KS0C1, KS0S1}

struct Cx { float re, im; };

__device__ __forceinline__ Cx cmul(Cx a, Cx b) {
    Cx r; r.re = a.re * b.re - a.im * b.im; r.im = a.re * b.im + a.im * b.re; return r;
}
__device__ __forceinline__ Cx cadd(Cx a, Cx b) { Cx r; r.re = a.re + b.re; r.im = a.im + b.im; return r; }

__device__ void apply_gate(Cx s[4], Cx m00, Cx m01, Cx m10, Cx m11, int q) {
    if (q == 0) {
        for (int j = 0; j < 2; j++) {
            Cx a = s[j], b = s[j + 2];
            s[j]     = cadd(cmul(m00, a), cmul(m01, b));
            s[j + 2] = cadd(cmul(m10, a), cmul(m11, b));
        }
    } else {
        for (int j = 0; j < 4; j += 2) {
            Cx a = s[j], b = s[j + 1];
            s[j]     = cadd(cmul(m00, a), cmul(m01, b));
            s[j + 1] = cadd(cmul(m10, a), cmul(m11, b));
        }
    }
}

// Single-warp setup: threads 0..3 each simulate one basis column,
// thread 0 assembles S and the 9 double-angle coefficients.
__global__ void build_K_kernel(const float* __restrict__ w) {
    __shared__ Cx U[4][4];   // U[k][b]
    int b = threadIdx.x;
    if (b < 4) {
        Cx s[4];
        for (int k = 0; k < 4; k++) { s[k].re = (k == b) ? 1.0f : 0.0f; s[k].im = 0.0f; }
        int off = 0;
        for (int layer = 0; layer < 2; layer++) {
            for (int q = 0; q < 2; q++) {
                float tx = w[off + q * 3 + 0];
                float tz = w[off + q * 3 + 1];
                float ty = w[off + q * 3 + 2];
                float c, sn;
                c = __cosf(0.5f * tx); sn = __sinf(0.5f * tx);
                { Cx m00{c,0}, m01{0,-sn}, m10{0,-sn}, m11{c,0};
                  apply_gate(s, m00, m01, m10, m11, q); }
                c = __cosf(0.5f * tz); sn = __sinf(0.5f * tz);
                { Cx m00{c,-sn}, m01{0,0}, m10{0,0}, m11{c,sn};
                  apply_gate(s, m00, m01, m10, m11, q); }
                c = __cosf(0.5f * ty); sn = __sinf(0.5f * ty);
                { Cx m00{c,0}, m01{-sn,0}, m10{sn,0}, m11{c,0};
                  apply_gate(s, m00, m01, m10, m11, q); }
            }
            Cx t = s[2]; s[2] = s[3]; s[3] = t;  // CNOT(0->1): swap |10>,|11>
            off += 6;
        }
        for (int k = 0; k < 4; k++) U[k][b] = s[k];
    }
    __syncthreads();
    if (threadIdx.x == 0) {
        float S[4][4];
        for (int i = 0; i < 4; i++)
            for (int j = 0; j < 4; j++) {
                float acc = 0.0f;
                for (int k = 0; k < 4; k++) {
                    float zk = (k < 2) ? 1.0f : -1.0f;
                    acc += zk * (U[k][i].re * U[k][j].re + U[k][i].im * U[k][j].im);
                }
                S[i][j] = acc;
            }
        float c0 = S[0][0], c1 = S[1][1], c2 = S[2][2], c3 = S[3][3];
        float c4 = 2.0f * S[0][1], c5 = 2.0f * S[0][2], c6 = 2.0f * S[0][3];
        float c7 = 2.0f * S[1][2], c8 = 2.0f * S[1][3], c9 = 2.0f * S[2][3];
        d_K[0] = 0.25f * (c0 + c1 + c2 + c3);   // 1
        d_K[1] = 0.25f * (c0 - c1 + c2 - c3);   // C1
        d_K[2] = 0.25f * (c4 + c9);             // S1
        d_K[3] = 0.25f * (c0 + c1 - c2 - c3);   // C0
        d_K[4] = 0.25f * (c0 - c1 - c2 + c3);   // C0*C1
        d_K[5] = 0.25f * (c4 - c9);             // C0*S1
        d_K[6] = 0.25f * (c5 + c8);             // S0
        d_K[7] = 0.25f * (c5 - c8);             // S0*C1
        d_K[8] = 0.25f * (c6 + c7);             // S0*S1
    }
}

__device__ __forceinline__ float eval_one(float x0, float x1, const float k[9]) {
    float S0, C0, S1, C1;
    __sincosf(CUDART_PI_F * x0, &S0, &C0);
    __sincosf(CUDART_PI_F * x1, &S1, &C1);
    float t1 = fmaf(k[2], S1, fmaf(k[1], C1, k[0]));
    float t2 = fmaf(k[5], S1, fmaf(k[4], C1, k[3]));
    float t3 = fmaf(k[8], S1, fmaf(k[7], C1, k[6]));
    return fmaf(S0, t3, fmaf(C0, t2, t1));
}

// 4 samples per thread: 2x float4 in, 1x float4 out.
__global__ void __launch_bounds__(256) qnn_main_kernel(
    const float4* __restrict__ in, float4* __restrict__ out, int n_quads) {
    int i = blockIdx.x * blockDim.x + threadIdx.x;
    float k[9];
#pragma unroll
    for (int j = 0; j < 9; j++) k[j] = d_K[j];
    if (i >= n_quads) return;
    float4 a = in[2 * i];
    float4 b = in[2 * i + 1];
    float4 r;
    r.x = eval_one(a.x, a.y, k);
    r.y = eval_one(a.z, a.w, k);
    r.z = eval_one(b.x, b.y, k);
    r.w = eval_one(b.z, b.w, k);
    out[i] = r;
}

// Scalar tail for B not divisible by 4 (not hit for B=4194304; zero cost).
__global__ void qnn_tail_kernel(const float2* __restrict__ in,
                                float* __restrict__ out, int start, int B) {
    int i = start + blockIdx.x * blockDim.x + threadIdx.x;
    if (i >= B) return;
    float k[9];
#pragma unroll
    for (int j = 0; j < 9; j++) k[j] = d_K[j];
    float2 x = in[i];
    out[i] = eval_one(x.x, x.y, k);
}

extern "C" void kernel_launch(void* const* d_in, const int* in_sizes, int n_in,
                              void* d_out, int out_size) {
    const float* inputs  = (const float*)d_in[0];   // [B,2]
    const float* weights = (const float*)d_in[1];   // [12]

    build_K_kernel<<<1, 32>>>(weights);

    int B = in_sizes[0] / 2;            // 4194304
    int n_quads = B / 4;                // 1048576
    if (n_quads > 0) {
        int threads = 256;
        int blocks = (n_quads + threads - 1) / threads;
        qnn_main_kernel<<<blocks, threads>>>((const float4*)inputs, (float4*)d_out, n_quads);
    }
    int done = n_quads * 4;
    if (done < B) {
        int rem = B - done;
        qnn_tail_kernel<<<(rem + 127) / 128, 128>>>((const float2*)inputs,
                                                    (float*)d_out, done, B);
    }
}